// round 14
// baseline (speedup 1.0000x reference)
#include <cuda_runtime.h>
#include <cuda_fp16.h>
#include <cstdint>
#include <math.h>

#define NH 8
#define HQ 1024
#define DD 128
#define NKV 8192
#define NCV 1024
#define TOT (NH*HQ*DD)
#define NCTA 148
#define NTHR 256

// ---------------- static scratch (no allocations allowed) ----------------
__device__ __align__(16) unsigned short g_qb[TOT];
__device__ __align__(16) unsigned short g_kb[NH*NKV*DD];
__device__ __align__(16) unsigned short g_vb[NH*NKV*DD];
__device__ __align__(16) unsigned short g_ckb[NH*NCV*DD];
__device__ __align__(16) unsigned short g_cvb[NH*NCV*DD];
__device__ __align__(16) __half g_z[TOT];
__device__ __align__(16) __half g_zc[TOT];
__device__ float g_part[NCTA];
__device__ int g_bar1, g_bar2, g_cnt;

// ---------------- ptx helpers ----------------
__device__ __forceinline__ void ldsm4(uint32_t& r0, uint32_t& r1, uint32_t& r2, uint32_t& r3, uint32_t a) {
  asm volatile("ldmatrix.sync.aligned.m8n8.x4.shared.b16 {%0,%1,%2,%3}, [%4];"
               : "=r"(r0), "=r"(r1), "=r"(r2), "=r"(r3) : "r"(a));
}
__device__ __forceinline__ void ldsm4t(uint32_t& r0, uint32_t& r1, uint32_t& r2, uint32_t& r3, uint32_t a) {
  asm volatile("ldmatrix.sync.aligned.m8n8.x4.trans.shared.b16 {%0,%1,%2,%3}, [%4];"
               : "=r"(r0), "=r"(r1), "=r"(r2), "=r"(r3) : "r"(a));
}
__device__ __forceinline__ void mma16816(float* c, const uint32_t* a, uint32_t b0, uint32_t b1) {
  asm volatile("mma.sync.aligned.m16n8k16.row.col.f32.f16.f16.f32 "
               "{%0,%1,%2,%3}, {%4,%5,%6,%7}, {%8,%9}, {%0,%1,%2,%3};"
               : "+f"(c[0]), "+f"(c[1]), "+f"(c[2]), "+f"(c[3])
               : "r"(a[0]), "r"(a[1]), "r"(a[2]), "r"(a[3]), "r"(b0), "r"(b1));
}
__device__ __forceinline__ void cpasync16(uint32_t saddr, const void* g) {
  asm volatile("cp.async.cg.shared.global [%0], [%1], 16;" :: "r"(saddr), "l"(g));
}
__device__ __forceinline__ void barg(int id) {
  asm volatile("bar.sync %0, 128;" :: "r"(id));
}
// all-resident cross-CTA barrier (release/acquire via threadfence + atomics)
__device__ __forceinline__ void grid_bar(int* ctr) {
  __syncthreads();
  if (threadIdx.x == 0) {
    __threadfence();
    atomicAdd(ctr, 1);
    while (atomicAdd(ctr, 0) < NCTA) { __nanosleep(64); }
    __threadfence();
  }
  __syncthreads();
}

#define Q4 262144
#define K4 2097152
#define CVT_TOT (3*Q4 + 2*K4)
#define CVT_PAIRS (CVT_TOT/2)   // 2,490,368

__device__ __forceinline__ void cvt_pair(int i2,
                                         const float4* __restrict__ q,
                                         const float4* __restrict__ k,
                                         const float4* __restrict__ v,
                                         const float4* __restrict__ ck,
                                         const float4* __restrict__ cv) {
  const float qscale = (float)(0.08838834764831845 * 1.4426950408889634);
  int i = i2 * 2;
  const float4* src; uint4* dst; float sc = 1.f; int off;
  if (i < Q4)              { src = q;  dst = (uint4*)g_qb;  off = i;              sc = qscale; }
  else if (i < Q4 + K4)    { src = k;  dst = (uint4*)g_kb;  off = i - Q4; }
  else if (i < Q4 + 2*K4)  { src = v;  dst = (uint4*)g_vb;  off = i - Q4 - K4; }
  else if (i < 2*Q4 + 2*K4){ src = ck; dst = (uint4*)g_ckb; off = i - Q4 - 2*K4; }
  else                     { src = cv; dst = (uint4*)g_cvb; off = i - 2*Q4 - 2*K4; }
  float4 a = src[off], b = src[off + 1];
  __half2 h0 = __float22half2_rn(make_float2(a.x * sc, a.y * sc));
  __half2 h1 = __float22half2_rn(make_float2(a.z * sc, a.w * sc));
  __half2 h2 = __float22half2_rn(make_float2(b.x * sc, b.y * sc));
  __half2 h3 = __float22half2_rn(make_float2(b.z * sc, b.w * sc));
  uint4 o;
  o.x = *(uint32_t*)&h0; o.y = *(uint32_t*)&h1;
  o.z = *(uint32_t*)&h2; o.w = *(uint32_t*)&h3;
  dst[off >> 1] = o;
}

// ---------------- fused persistent kernel: cvt | attention | mse ----------------
// attn smem: Q 16KB | gA K dbuf 32KB | gA V dbuf 32KB | gB K dbuf 32KB | gB V dbuf 32KB
#define SM_Q 0
#define SM_GA 16384
#define SMEM_BYTES 147456
#define PADC 132

__global__ void __launch_bounds__(NTHR, 1)
fused_kernel(const float4* __restrict__ qin, const float4* __restrict__ kin,
             const float4* __restrict__ vin, const float4* __restrict__ ckin,
             const float4* __restrict__ cvin, float* __restrict__ out) {
  extern __shared__ char smem[];
  const uint32_t smb = (uint32_t)__cvta_generic_to_shared(smem);
  const int tid = threadIdx.x;
  const int bid = blockIdx.x;

  // ================= phase 1: fp32 -> fp16 convert =================
  {
    const int stride = NCTA * NTHR;                 // 37888
    int i2 = bid * NTHR + tid;
    for (; i2 + stride < CVT_PAIRS; i2 += 2 * stride) {   // 2 independent pairs in flight
      cvt_pair(i2, qin, kin, vin, ckin, cvin);
      cvt_pair(i2 + stride, qin, kin, vin, ckin, cvin);
    }
    if (i2 < CVT_PAIRS) cvt_pair(i2, qin, kin, vin, ckin, cvin);
  }
  grid_bar(&g_bar1);

  // ================= phase 2: mma flash attention (R12 config) =================
  const int lane = tid & 31, warp = tid >> 5;
  const int group = warp >> 2, gwarp = warp & 3;
  const int gtid = tid & 127;
  const int g = lane >> 2, tig = lane & 3;
  const int within = lane & 7, sub = lane >> 3;
  const int rql = ((sub & 1) << 3) + within;
  const int csel = sub >> 1;
  const int barid = 1 + group;

  int it0 = 0, nit = 1;
  if (bid >= 128) { int b = bid - 128; it0 = (b * 128) / 20; nit = ((b + 1) * 128) / 20 - it0; }

  const uint32_t kgbase = smb + SM_GA + group * 65536;
  const uint32_t vgbase = kgbase + 32768;

  for (int ii = 0; ii < nit; ii++) {
    const unsigned short* Kb; const unsigned short* Vb; __half* Og; int n_kv; int lb;
    if (bid < 128) { Kb = g_kb;  Vb = g_vb;  Og = g_z;  n_kv = NKV; lb = bid; }
    else           { Kb = g_ckb; Vb = g_cvb; Og = g_zc; n_kv = NCV; lb = it0 + ii; }
    const int h = lb >> 4, qt = lb & 15;
    const int qrow0 = h * HQ + qt * 64;

    const int half = n_kv >> 1;
    const int Tg = half >> 6;
    const unsigned short* khalf = Kb + ((size_t)h * n_kv + (size_t)group * half) * DD;
    const unsigned short* vhalf = Vb + ((size_t)h * n_kv + (size_t)group * half) * DD;

    {
      const unsigned short* qs = g_qb + (size_t)qrow0 * DD;
      for (int i = tid; i < 1024; i += NTHR) {
        int r = i >> 4, c = i & 15;
        uint32_t off = r * 256 + ((c ^ (r & 7)) << 4);
        cpasync16(smb + SM_Q + off, qs + r * DD + c * 8);
      }
      for (int i = gtid; i < 1024; i += 128) {
        int r = i >> 4, c = i & 15;
        uint32_t off = r * 256 + ((c ^ (r & 7)) << 4);
        cpasync16(kgbase + off, khalf + r * DD + c * 8);
        cpasync16(vgbase + off, vhalf + r * DD + c * 8);
      }
      asm volatile("cp.async.commit_group;");
    }
    asm volatile("cp.async.wait_group 0;");
    __syncthreads();

    uint32_t qa[8][4];
#pragma unroll
    for (int kt = 0; kt < 8; kt++) {
      int r = gwarp * 16 + rql, c = 2 * kt + csel;
      ldsm4(qa[kt][0], qa[kt][1], qa[kt][2], qa[kt][3],
            smb + SM_Q + r * 256 + ((c ^ (r & 7)) << 4));
    }

    float o[16][4];
#pragma unroll
    for (int i = 0; i < 16; i++) { o[i][0] = o[i][1] = o[i][2] = o[i][3] = 0.f; }
    float rs0 = 0.f, rs1 = 0.f;

    for (int t = 0; t < Tg; t++) {
      const int buf = t & 1;
      asm volatile("cp.async.wait_group 0;");
      barg(barid);
      if (t + 1 < Tg) {
        const unsigned short* ks = khalf + (size_t)(t + 1) * 64 * DD;
        const unsigned short* vs = vhalf + (size_t)(t + 1) * 64 * DD;
        const int bo = (buf ^ 1) * 16384;
        for (int i = gtid; i < 1024; i += 128) {
          int r = i >> 4, c = i & 15;
          uint32_t off = r * 256 + ((c ^ (r & 7)) << 4);
          cpasync16(kgbase + bo + off, ks + r * DD + c * 8);
          cpasync16(vgbase + bo + off, vs + r * DD + c * 8);
        }
        asm volatile("cp.async.commit_group;");
      }

      float s[8][4];
#pragma unroll
      for (int j = 0; j < 8; j++) { s[j][0] = s[j][1] = s[j][2] = s[j][3] = 0.f; }
      const uint32_t kbase = kgbase + buf * 16384;
#pragma unroll
      for (int kt = 0; kt < 8; kt++) {
#pragma unroll
        for (int np = 0; np < 4; np++) {
          int r = 16 * np + rql, c = 2 * kt + csel;
          uint32_t b0, b1, b2, b3;
          ldsm4(b0, b1, b2, b3, kbase + r * 256 + ((c ^ (r & 7)) << 4));
          mma16816(s[2 * np], qa[kt], b0, b2);
          mma16816(s[2 * np + 1], qa[kt], b1, b3);
        }
      }

      uint32_t p[8][2];
      __half2 lt0 = __float2half2_rn(0.f), lt1 = __float2half2_rn(0.f);
#pragma unroll
      for (int j = 0; j < 8; j++) {
        __half2 a = h2exp2(__float22half2_rn(make_float2(s[j][0], s[j][1])));
        __half2 b = h2exp2(__float22half2_rn(make_float2(s[j][2], s[j][3])));
        lt0 = __hadd2(lt0, a);
        lt1 = __hadd2(lt1, b);
        p[j][0] = *(uint32_t*)&a;
        p[j][1] = *(uint32_t*)&b;
      }
      rs0 += __low2float(lt0) + __high2float(lt0);
      rs1 += __low2float(lt1) + __high2float(lt1);

      const uint32_t vbase = vgbase + buf * 16384;
#pragma unroll
      for (int kt2 = 0; kt2 < 4; kt2++) {
        uint32_t pa[4] = {p[2 * kt2][0], p[2 * kt2][1], p[2 * kt2 + 1][0], p[2 * kt2 + 1][1]};
#pragma unroll
        for (int dp = 0; dp < 8; dp++) {
          int r = 16 * kt2 + rql, c = 2 * dp + csel;
          uint32_t v0, v1, v2, v3;
          ldsm4t(v0, v1, v2, v3, vbase + r * 256 + ((c ^ (r & 7)) << 4));
          mma16816(o[2 * dp], pa, v0, v1);
          mma16816(o[2 * dp + 1], pa, v2, v3);
        }
      }
    }

    rs0 += __shfl_xor_sync(~0u, rs0, 1); rs0 += __shfl_xor_sync(~0u, rs0, 2);
    rs1 += __shfl_xor_sync(~0u, rs1, 1); rs1 += __shfl_xor_sync(~0u, rs1, 2);

    __syncthreads();
    float* OBs = (float*)(smem + SM_GA);
    float* lBs = (float*)(smem + SM_GA + 64 * PADC * 4);
    const int r0 = 16 * gwarp + g;

    if (group == 1) {
      if (tig == 0) { lBs[r0] = rs0; lBs[r0 + 8] = rs1; }
#pragma unroll
      for (int dt = 0; dt < 16; dt++) {
        int col = 8 * dt + 2 * tig;
        *(float2*)&OBs[r0 * PADC + col]       = make_float2(o[dt][0], o[dt][1]);
        *(float2*)&OBs[(r0 + 8) * PADC + col] = make_float2(o[dt][2], o[dt][3]);
      }
    }
    __syncthreads();

    if (group == 0) {
      const float inv0 = 1.f / (rs0 + lBs[r0]);
      const float inv1 = 1.f / (rs1 + lBs[r0 + 8]);
      const int row0 = qrow0 + r0;
#pragma unroll
      for (int dt = 0; dt < 16; dt++) {
        int col = 8 * dt + 2 * tig;
        float2 b0 = *(float2*)&OBs[r0 * PADC + col];
        float2 b1 = *(float2*)&OBs[(r0 + 8) * PADC + col];
        __half2 w0 = __float22half2_rn(make_float2((o[dt][0] + b0.x) * inv0,
                                                   (o[dt][1] + b0.y) * inv0));
        __half2 w1 = __float22half2_rn(make_float2((o[dt][2] + b1.x) * inv1,
                                                   (o[dt][3] + b1.y) * inv1));
        *(__half2*)(Og + (size_t)row0 * DD + col) = w0;
        *(__half2*)(Og + (size_t)(row0 + 8) * DD + col) = w1;
      }
    }
    __syncthreads();
  }

  // ================= phase 3: fused MSE =================
  grid_bar(&g_bar2);
  {
    float s = 0.f;
    const __half2* zp  = (const __half2*)g_z;
    const __half2* zcp = (const __half2*)g_zc;
    for (int i = bid * NTHR + tid; i < TOT / 2; i += NCTA * NTHR) {
      float2 a = __half22float2(zp[i]);
      float2 b = __half22float2(zcp[i]);
      float d0 = a.x - b.x, d1 = a.y - b.y;
      s += d0 * d0 + d1 * d1;
    }
    float* red = (float*)smem;
    int* flag = (int*)(smem + NTHR * 4);
    red[tid] = s; __syncthreads();
    for (int o = 128; o > 0; o >>= 1) { if (tid < o) red[tid] += red[tid + o]; __syncthreads(); }
    if (tid == 0) {
      g_part[bid] = red[0];
      __threadfence();
      *flag = (atomicAdd(&g_cnt, 1) == NCTA - 1);
    }
    __syncthreads();
    if (*flag) {
      __threadfence();
      red[tid] = (tid < NCTA) ? g_part[tid] : 0.f;
      __syncthreads();
      for (int o = 128; o > 0; o >>= 1) { if (tid < o) red[tid] += red[tid + o]; __syncthreads(); }
      if (tid == 0) {
        out[0] = red[0] * (1.0f / (float)TOT);
        g_cnt = 0; g_bar1 = 0; g_bar2 = 0;   // reset for next graph replay
      }
    }
  }
}

extern "C" void kernel_launch(void* const* d_in, const int* in_sizes, int n_in,
                              void* d_out, int out_size) {
  const float* q  = (const float*)d_in[0];
  const float* k  = (const float*)d_in[1];
  const float* v  = (const float*)d_in[2];
  const float* ck = (const float*)d_in[3];
  const float* cv = (const float*)d_in[4];
  (void)in_sizes; (void)n_in; (void)out_size;

  cudaFuncSetAttribute(fused_kernel,
                       cudaFuncAttributeMaxDynamicSharedMemorySize, SMEM_BYTES);

  fused_kernel<<<NCTA, NTHR, SMEM_BYTES>>>((const float4*)q, (const float4*)k,
                                           (const float4*)v, (const float4*)ck,
                                           (const float4*)cv, (float*)d_out);
}

// round 15
// speedup vs baseline: 1.2522x; 1.2522x over previous
#include <cuda_runtime.h>
#include <cuda_fp16.h>
#include <cstdint>
#include <math.h>

#define NH 8
#define HQ 1024
#define DD 128
#define NKV 8192
#define NCV 1024
#define TOT (NH*HQ*DD)

// ---------------- static scratch (no allocations allowed) ----------------
__device__ __align__(16) unsigned short g_qb[TOT];         // Q fp16 (pre-scaled)
__device__ __align__(16) unsigned short g_kb[NH*NKV*DD];   // K fp16
__device__ __align__(16) unsigned short g_vb[NH*NKV*DD];   // V fp16
__device__ __align__(16) unsigned short g_ckb[NH*NCV*DD];  // cK fp16
__device__ __align__(16) unsigned short g_cvb[NH*NCV*DD];  // cV fp16
__device__ __align__(16) __half g_z[TOT];                  // z fp16
__device__ __align__(16) __half g_zc[TOT];                 // zc fp16
__device__ float g_part[256];
__device__ int g_cnt;

// ---------------- ptx helpers ----------------
__device__ __forceinline__ void ldsm4(uint32_t& r0, uint32_t& r1, uint32_t& r2, uint32_t& r3, uint32_t a) {
  asm volatile("ldmatrix.sync.aligned.m8n8.x4.shared.b16 {%0,%1,%2,%3}, [%4];"
               : "=r"(r0), "=r"(r1), "=r"(r2), "=r"(r3) : "r"(a));
}
__device__ __forceinline__ void ldsm4t(uint32_t& r0, uint32_t& r1, uint32_t& r2, uint32_t& r3, uint32_t a) {
  asm volatile("ldmatrix.sync.aligned.m8n8.x4.trans.shared.b16 {%0,%1,%2,%3}, [%4];"
               : "=r"(r0), "=r"(r1), "=r"(r2), "=r"(r3) : "r"(a));
}
__device__ __forceinline__ void mma16816(float* c, const uint32_t* a, uint32_t b0, uint32_t b1) {
  asm volatile("mma.sync.aligned.m16n8k16.row.col.f32.f16.f16.f32 "
               "{%0,%1,%2,%3}, {%4,%5,%6,%7}, {%8,%9}, {%0,%1,%2,%3};"
               : "+f"(c[0]), "+f"(c[1]), "+f"(c[2]), "+f"(c[3])
               : "r"(a[0]), "r"(a[1]), "r"(a[2]), "r"(a[3]), "r"(b0), "r"(b1));
}
__device__ __forceinline__ void cpasync16(uint32_t saddr, const void* g) {
  asm volatile("cp.async.cg.shared.global [%0], [%1], 16;" :: "r"(saddr), "l"(g));
}
__device__ __forceinline__ void barg(int id) {  // group-scoped barrier, 128 threads
  asm volatile("bar.sync %0, 128;" :: "r"(id));
}

// ---------------- fused fp32 -> fp16 convert, 2x float4 per thread ----------------
#define Q4 262144
#define K4 2097152
#define CVT_TOT (3*Q4 + 2*K4)
#define CVT_PAIRS (CVT_TOT/2)

__global__ void cvt_all_kernel(const float4* __restrict__ q,
                               const float4* __restrict__ k,
                               const float4* __restrict__ v,
                               const float4* __restrict__ ck,
                               const float4* __restrict__ cv) {
  const float qscale = (float)(0.08838834764831845 * 1.4426950408889634);
  int p = blockIdx.x * 256 + threadIdx.x;
  int i = p * 2;
  const float4* src; uint4* dst; float sc = 1.f; int off;
  if (i < Q4)              { src = q;  dst = (uint4*)g_qb;  off = i;              sc = qscale; }
  else if (i < Q4 + K4)    { src = k;  dst = (uint4*)g_kb;  off = i - Q4; }
  else if (i < Q4 + 2*K4)  { src = v;  dst = (uint4*)g_vb;  off = i - Q4 - K4; }
  else if (i < 2*Q4 + 2*K4){ src = ck; dst = (uint4*)g_ckb; off = i - Q4 - 2*K4; }
  else                     { src = cv; dst = (uint4*)g_cvb; off = i - 2*Q4 - 2*K4; }
  float4 a = src[off], b = src[off + 1];
  __half2 h0 = __float22half2_rn(make_float2(a.x * sc, a.y * sc));
  __half2 h1 = __float22half2_rn(make_float2(a.z * sc, a.w * sc));
  __half2 h2 = __float22half2_rn(make_float2(b.x * sc, b.y * sc));
  __half2 h3 = __float22half2_rn(make_float2(b.z * sc, b.w * sc));
  uint4 o;
  o.x = *(uint32_t*)&h0; o.y = *(uint32_t*)&h1;
  o.z = *(uint32_t*)&h2; o.w = *(uint32_t*)&h3;
  dst[off >> 1] = o;
}

// ---------------- mma flash attention, dual split-KV groups, 1 barrier/tile ----------------
// smem: Q 16KB | groupA K dbuf 32KB | groupA V dbuf 32KB | groupB K dbuf 32KB | groupB V dbuf 32KB
#define SM_Q 0
#define SM_GA 16384
#define SMEM_BYTES 147456
#define PADC 132           // merge buffer row stride (floats)

__global__ void __launch_bounds__(256, 1)
attn_mma_kernel() {
  extern __shared__ char smem[];
  const uint32_t smb = (uint32_t)__cvta_generic_to_shared(smem);
  const int tid = threadIdx.x;
  const int lane = tid & 31, warp = tid >> 5;
  const int group = warp >> 2, gwarp = warp & 3;
  const int gtid = tid & 127;
  const int g = lane >> 2, tig = lane & 3;
  const int within = lane & 7, sub = lane >> 3;
  const int rql = ((sub & 1) << 3) + within;
  const int csel = sub >> 1;
  const int barid = 1 + group;
  const int bid = blockIdx.x;

  // balanced static schedule over 148 CTAs
  int it0 = 0, nit = 1;
  if (bid >= 128) { int b = bid - 128; it0 = (b * 128) / 20; nit = ((b + 1) * 128) / 20 - it0; }

  const uint32_t kgbase = smb + SM_GA + group * 65536;        // K dbuf
  const uint32_t vgbase = kgbase + 32768;                      // V dbuf

  for (int ii = 0; ii < nit; ii++) {
    const unsigned short* Kb; const unsigned short* Vb; __half* Og; int n_kv; int lb;
    if (bid < 128) { Kb = g_kb;  Vb = g_vb;  Og = g_z;  n_kv = NKV; lb = bid; }
    else           { Kb = g_ckb; Vb = g_cvb; Og = g_zc; n_kv = NCV; lb = it0 + ii; }
    const int h = lb >> 4, qt = lb & 15;
    const int qrow0 = h * HQ + qt * 64;

    const int half = n_kv >> 1;
    const int Tg = half >> 6;                        // BN=64 tiles per group
    const unsigned short* khalf = Kb + ((size_t)h * n_kv + (size_t)group * half) * DD;
    const unsigned short* vhalf = Vb + ((size_t)h * n_kv + (size_t)group * half) * DD;

    // ---- prologue: Q (all threads) + this group's K0/V0 ----
    {
      const unsigned short* qs = g_qb + (size_t)qrow0 * DD;
      for (int i = tid; i < 1024; i += 256) {
        int r = i >> 4, c = i & 15;
        uint32_t off = r * 256 + ((c ^ (r & 7)) << 4);
        cpasync16(smb + SM_Q + off, qs + r * DD + c * 8);
      }
      for (int i = gtid; i < 1024; i += 128) {
        int r = i >> 4, c = i & 15;
        uint32_t off = r * 256 + ((c ^ (r & 7)) << 4);
        cpasync16(kgbase + off, khalf + r * DD + c * 8);
        cpasync16(vgbase + off, vhalf + r * DD + c * 8);
      }
      asm volatile("cp.async.commit_group;");
    }
    asm volatile("cp.async.wait_group 0;");
    __syncthreads();

    // ---- Q fragments ----
    uint32_t qa[8][4];
#pragma unroll
    for (int kt = 0; kt < 8; kt++) {
      int r = gwarp * 16 + rql, c = 2 * kt + csel;
      ldsm4(qa[kt][0], qa[kt][1], qa[kt][2], qa[kt][3],
            smb + SM_Q + r * 256 + ((c ^ (r & 7)) << 4));
    }

    float o[16][4];
#pragma unroll
    for (int i = 0; i < 16; i++) { o[i][0] = o[i][1] = o[i][2] = o[i][3] = 0.f; }
    float rs0 = 0.f, rs1 = 0.f;

    for (int t = 0; t < Tg; t++) {
      const int buf = t & 1;
      // tile t landed; arrival at barg proves all warps done with buf^1 -> safe to refill
      asm volatile("cp.async.wait_group 0;");
      barg(barid);
      if (t + 1 < Tg) {
        const unsigned short* ks = khalf + (size_t)(t + 1) * 64 * DD;
        const unsigned short* vs = vhalf + (size_t)(t + 1) * 64 * DD;
        const int bo = (buf ^ 1) * 16384;
        for (int i = gtid; i < 1024; i += 128) {
          int r = i >> 4, c = i & 15;
          uint32_t off = r * 256 + ((c ^ (r & 7)) << 4);
          cpasync16(kgbase + bo + off, ks + r * DD + c * 8);
          cpasync16(vgbase + bo + off, vs + r * DD + c * 8);
        }
        asm volatile("cp.async.commit_group;");
      }

      // ---- GEMM1: S = Q K^T (base-2 logits), f32 acc ----
      float s[8][4];
#pragma unroll
      for (int j = 0; j < 8; j++) { s[j][0] = s[j][1] = s[j][2] = s[j][3] = 0.f; }
      const uint32_t kbase = kgbase + buf * 16384;
#pragma unroll
      for (int kt = 0; kt < 8; kt++) {
#pragma unroll
        for (int np = 0; np < 4; np++) {
          int r = 16 * np + rql, c = 2 * kt + csel;
          uint32_t b0, b1, b2, b3;
          ldsm4(b0, b1, b2, b3, kbase + r * 256 + ((c ^ (r & 7)) << 4));
          mma16816(s[2 * np], qa[kt], b0, b2);
          mma16816(s[2 * np + 1], qa[kt], b1, b3);
        }
      }

      // ---- packed fp16 no-max softmax: p = 2^s ----
      uint32_t p[8][2];
      __half2 lt0 = __float2half2_rn(0.f), lt1 = __float2half2_rn(0.f);
#pragma unroll
      for (int j = 0; j < 8; j++) {
        __half2 a = h2exp2(__float22half2_rn(make_float2(s[j][0], s[j][1])));
        __half2 b = h2exp2(__float22half2_rn(make_float2(s[j][2], s[j][3])));
        lt0 = __hadd2(lt0, a);
        lt1 = __hadd2(lt1, b);
        p[j][0] = *(uint32_t*)&a;
        p[j][1] = *(uint32_t*)&b;
      }
      rs0 += __low2float(lt0) + __high2float(lt0);
      rs1 += __low2float(lt1) + __high2float(lt1);

      // ---- GEMM2: O += P V, f32 acc ----
      const uint32_t vbase = vgbase + buf * 16384;
#pragma unroll
      for (int kt2 = 0; kt2 < 4; kt2++) {
        uint32_t pa[4] = {p[2 * kt2][0], p[2 * kt2][1], p[2 * kt2 + 1][0], p[2 * kt2 + 1][1]};
#pragma unroll
        for (int dp = 0; dp < 8; dp++) {
          int r = 16 * kt2 + rql, c = 2 * dp + csel;
          uint32_t v0, v1, v2, v3;
          ldsm4t(v0, v1, v2, v3, vbase + r * 256 + ((c ^ (r & 7)) << 4));
          mma16816(o[2 * dp], pa, v0, v1);
          mma16816(o[2 * dp + 1], pa, v2, v3);
        }
      }
    }

    // ---- final l reduction (quad) ----
    rs0 += __shfl_xor_sync(~0u, rs0, 1); rs0 += __shfl_xor_sync(~0u, rs0, 2);
    rs1 += __shfl_xor_sync(~0u, rs1, 1); rs1 += __shfl_xor_sync(~0u, rs1, 2);

    // ---- additive merge of the two groups via smem ----
    __syncthreads();
    float* OBs = (float*)(smem + SM_GA);
    float* lBs = (float*)(smem + SM_GA + 64 * PADC * 4);
    const int r0 = 16 * gwarp + g;

    if (group == 1) {
      if (tig == 0) { lBs[r0] = rs0; lBs[r0 + 8] = rs1; }
#pragma unroll
      for (int dt = 0; dt < 16; dt++) {
        int col = 8 * dt + 2 * tig;
        *(float2*)&OBs[r0 * PADC + col]       = make_float2(o[dt][0], o[dt][1]);
        *(float2*)&OBs[(r0 + 8) * PADC + col] = make_float2(o[dt][2], o[dt][3]);
      }
    }
    __syncthreads();

    if (group == 0) {
      const float inv0 = 1.f / (rs0 + lBs[r0]);
      const float inv1 = 1.f / (rs1 + lBs[r0 + 8]);
      const int row0 = qrow0 + r0;
#pragma unroll
      for (int dt = 0; dt < 16; dt++) {
        int col = 8 * dt + 2 * tig;
        float2 b0 = *(float2*)&OBs[r0 * PADC + col];
        float2 b1 = *(float2*)&OBs[(r0 + 8) * PADC + col];
        __half2 w0 = __float22half2_rn(make_float2((o[dt][0] + b0.x) * inv0,
                                                   (o[dt][1] + b0.y) * inv0));
        __half2 w1 = __float22half2_rn(make_float2((o[dt][2] + b1.x) * inv1,
                                                   (o[dt][3] + b1.y) * inv1));
        *(__half2*)(Og + (size_t)row0 * DD + col) = w0;
        *(__half2*)(Og + (size_t)(row0 + 8) * DD + col) = w1;
      }
    }
    __syncthreads();   // merge reads done before next item overwrites smem
  }
}

// ---------------- fused deterministic MSE over fp16 z/zc ----------------
__global__ void mse_kernel(float* __restrict__ out) {
  __shared__ float red[256];
  __shared__ int lastflag;
  const int bid = blockIdx.x, tid = threadIdx.x;
  const __half2* zp  = (const __half2*)g_z  + (size_t)bid * 2048;
  const __half2* zcp = (const __half2*)g_zc + (size_t)bid * 2048;
  float s = 0.f;
  for (int i = tid; i < 2048; i += 256) {
    float2 a = __half22float2(zp[i]);
    float2 b = __half22float2(zcp[i]);
    float d0 = a.x - b.x, d1 = a.y - b.y;
    s += d0 * d0 + d1 * d1;
  }
  red[tid] = s; __syncthreads();
  for (int o = 128; o > 0; o >>= 1) { if (tid < o) red[tid] += red[tid + o]; __syncthreads(); }
  if (tid == 0) {
    g_part[bid] = red[0];
    __threadfence();
    lastflag = (atomicAdd(&g_cnt, 1) == 255);
  }
  __syncthreads();
  if (lastflag) {
    __threadfence();
    red[tid] = g_part[tid];
    __syncthreads();
    for (int o = 128; o > 0; o >>= 1) { if (tid < o) red[tid] += red[tid + o]; __syncthreads(); }
    if (tid == 0) { out[0] = red[0] * (1.0f / (float)TOT); g_cnt = 0; }
  }
}

extern "C" void kernel_launch(void* const* d_in, const int* in_sizes, int n_in,
                              void* d_out, int out_size) {
  const float* q  = (const float*)d_in[0];
  const float* k  = (const float*)d_in[1];
  const float* v  = (const float*)d_in[2];
  const float* ck = (const float*)d_in[3];
  const float* cv = (const float*)d_in[4];
  (void)in_sizes; (void)n_in; (void)out_size;

  cudaFuncSetAttribute(attn_mma_kernel,
                       cudaFuncAttributeMaxDynamicSharedMemorySize, SMEM_BYTES);

  cvt_all_kernel<<<CVT_PAIRS / 256, 256>>>((const float4*)q, (const float4*)k,
                                           (const float4*)v, (const float4*)ck,
                                           (const float4*)cv);
  attn_mma_kernel<<<148, 256, SMEM_BYTES>>>();
  mse_kernel<<<256, 256>>>((float*)d_out);
}